// round 6
// baseline (speedup 1.0000x reference)
#include <cuda_runtime.h>
#include <cuda_fp16.h>

#define NP 110000
#define NT 20000
#define NG 10000
#define NTOT (NP + NT + NG)   // 140000
#define EE 500000
#define DD 64

#define SCAN_CHUNK 1024
#define NBLK ((NTOT + SCAN_CHUNK - 1) / SCAN_CHUNK)   // 137

// ---- scratch (static device memory; no allocations allowed) ----
__device__ int   g_deg[NTOT];
__device__ int   g_off[NTOT + 1];
__device__ int   g_cur[NTOT];
__device__ int   g_bsum[NBLK];
__device__ int   g_boff[NBLK];
__device__ int   g_adj[3 * EE];
__device__ float g_dinv[NTOT];
__device__ __align__(16) __half g_embh[(size_t)NTOT * DD];  // fp16 embeddings
__device__ __align__(16) __half g_x1h[(size_t)NTOT * DD];   // layer-1 output
__device__ __align__(16) __half g_x2h[(size_t)NTOT * DD];   // final table p

// ---------------------------------------------------------------
__global__ void convert_kernel(const float* __restrict__ e0,
                               const float* __restrict__ e1,
                               const float* __restrict__ e2) {
    const int n0 = NP * DD / 8, n1 = NT * DD / 8, n2 = NG * DD / 8;
    int i = blockIdx.x * blockDim.x + threadIdx.x;
    const float4* src; __half* dst; int j;
    if (i < n0)                { src = (const float4*)e0; dst = g_embh;                          j = i; }
    else if (i < n0 + n1)      { src = (const float4*)e1; dst = g_embh + (size_t)NP * DD;        j = i - n0; }
    else if (i < n0 + n1 + n2) { src = (const float4*)e2; dst = g_embh + (size_t)(NP + NT) * DD; j = i - n0 - n1; }
    else return;
    float4 a = src[(size_t)j * 2], b = src[(size_t)j * 2 + 1];
    __half2 h0 = __floats2half2_rn(a.x, a.y), h1 = __floats2half2_rn(a.z, a.w);
    __half2 h2 = __floats2half2_rn(b.x, b.y), h3 = __floats2half2_rn(b.z, b.w);
    uint4 u;
    u.x = *reinterpret_cast<unsigned*>(&h0);
    u.y = *reinterpret_cast<unsigned*>(&h1);
    u.z = *reinterpret_cast<unsigned*>(&h2);
    u.w = *reinterpret_cast<unsigned*>(&h3);
    *reinterpret_cast<uint4*>(dst + (size_t)j * 8) = u;
}

__global__ void degree_kernel(const int* __restrict__ up,
                              const int* __restrict__ ut,
                              const int* __restrict__ ug) {
    const int Q = EE / 4;
    int i = blockIdx.x * blockDim.x + threadIdx.x;
    if (i < Q) {
        int4 d = reinterpret_cast<const int4*>(up + EE)[i];
        atomicAdd(&g_deg[d.x], 1); atomicAdd(&g_deg[d.y], 1);
        atomicAdd(&g_deg[d.z], 1); atomicAdd(&g_deg[d.w], 1);
    } else if (i < 2 * Q) {
        int4 d = reinterpret_cast<const int4*>(ut + EE)[i - Q];
        atomicAdd(&g_deg[NP + d.x], 1); atomicAdd(&g_deg[NP + d.y], 1);
        atomicAdd(&g_deg[NP + d.z], 1); atomicAdd(&g_deg[NP + d.w], 1);
    } else if (i < 3 * Q) {
        int4 d = reinterpret_cast<const int4*>(ug + EE)[i - 2 * Q];
        atomicAdd(&g_deg[NP + NT + d.x], 1); atomicAdd(&g_deg[NP + NT + d.y], 1);
        atomicAdd(&g_deg[NP + NT + d.z], 1); atomicAdd(&g_deg[NP + NT + d.w], 1);
    }
}

__global__ void scan1_kernel() {
    __shared__ int wsum[8];
    int blk = blockIdx.x;
    int t = threadIdx.x;
    int lane = t & 31, wid = t >> 5;
    int base = blk * SCAN_CHUNK + t * 4;

    int v0 = 0, v1 = 0, v2 = 0, v3 = 0;
    if (base + 3 < NTOT) {
        v0 = g_deg[base]; v1 = g_deg[base + 1];
        v2 = g_deg[base + 2]; v3 = g_deg[base + 3];
    } else {
        if (base     < NTOT) v0 = g_deg[base];
        if (base + 1 < NTOT) v1 = g_deg[base + 1];
        if (base + 2 < NTOT) v2 = g_deg[base + 2];
        if (base + 3 < NTOT) v3 = g_deg[base + 3];
    }
    int s = v0 + v1 + v2 + v3;
    int inc = s;
#pragma unroll
    for (int o = 1; o < 32; o <<= 1) {
        int n = __shfl_up_sync(0xffffffffu, inc, o);
        if (lane >= o) inc += n;
    }
    if (lane == 31) wsum[wid] = inc;
    __syncthreads();
    if (t == 0) {
        int run = 0;
#pragma unroll
        for (int w = 0; w < 8; w++) { int x = wsum[w]; wsum[w] = run; run += x; }
        g_bsum[blk] = run;
    }
    __syncthreads();
    int ex = inc - s + wsum[wid];
    if (base     < NTOT) g_off[base]     = ex;
    if (base + 1 < NTOT) g_off[base + 1] = ex + v0;
    if (base + 2 < NTOT) g_off[base + 2] = ex + v0 + v1;
    if (base + 3 < NTOT) g_off[base + 3] = ex + v0 + v1 + v2;
}

__global__ void scan2_kernel() {
    __shared__ int sh[256];
    int t = threadIdx.x;
    int v = (t < NBLK) ? g_bsum[t] : 0;
    sh[t] = v;
    __syncthreads();
    for (int o = 1; o < 256; o <<= 1) {
        int n = (t >= o) ? sh[t - o] : 0;
        __syncthreads();
        sh[t] += n;
        __syncthreads();
    }
    if (t < NBLK) g_boff[t] = sh[t] - v;
    if (t == 255) g_off[NTOT] = sh[255];
}

__global__ void scan3_kernel() {
    int i = blockIdx.x * blockDim.x + threadIdx.x;
    if (i >= NTOT) return;
    int off = g_off[i] + g_boff[i >> 10];
    g_off[i] = off;
    g_cur[i] = off;
    int d = g_deg[i];
    g_dinv[i] = (d > 0) ? rsqrtf((float)d) : 0.f;
}

__global__ void build_adj_kernel(const int* __restrict__ up,
                                 const int* __restrict__ ut,
                                 const int* __restrict__ ug) {
    const int Q = EE / 4;
    int i = blockIdx.x * blockDim.x + threadIdx.x;
    if (i < Q) {
        int4 s = reinterpret_cast<const int4*>(up)[i];
        int4 d = reinterpret_cast<const int4*>(up + EE)[i];
        g_adj[atomicAdd(&g_cur[d.x], 1)] = s.x;
        g_adj[atomicAdd(&g_cur[d.y], 1)] = s.y;
        g_adj[atomicAdd(&g_cur[d.z], 1)] = s.z;
        g_adj[atomicAdd(&g_cur[d.w], 1)] = s.w;
    } else if (i < 2 * Q) {
        int4 s = reinterpret_cast<const int4*>(ut)[i - Q];
        int4 d = reinterpret_cast<const int4*>(ut + EE)[i - Q];
        g_adj[atomicAdd(&g_cur[NP + d.x], 1)] = s.x;
        g_adj[atomicAdd(&g_cur[NP + d.y], 1)] = s.y;
        g_adj[atomicAdd(&g_cur[NP + d.z], 1)] = s.z;
        g_adj[atomicAdd(&g_cur[NP + d.w], 1)] = s.w;
    } else if (i < 3 * Q) {
        int4 s = reinterpret_cast<const int4*>(ug)[i - 2 * Q];
        int4 d = reinterpret_cast<const int4*>(ug + EE)[i - 2 * Q];
        g_adj[atomicAdd(&g_cur[NP + NT + d.x], 1)] = s.x;
        g_adj[atomicAdd(&g_cur[NP + NT + d.y], 1)] = s.y;
        g_adj[atomicAdd(&g_cur[NP + NT + d.z], 1)] = s.z;
        g_adj[atomicAdd(&g_cur[NP + NT + d.w], 1)] = s.w;
    }
}

// ---------------------------------------------------------------
__device__ __forceinline__ float4 load_h4(const __half* __restrict__ tab,
                                          int s, int o) {
    uint2 r = *reinterpret_cast<const uint2*>(tab + (size_t)s * DD + o);
    __half2 a = *reinterpret_cast<__half2*>(&r.x);
    __half2 b = *reinterpret_cast<__half2*>(&r.y);
    float2 fa = __half22float2(a), fb = __half22float2(b);
    return make_float4(fa.x, fa.y, fb.x, fb.y);
}

__device__ __forceinline__ void store_h4(__half* __restrict__ dst,
                                         int n, int o, float4 v) {
    __half2 a = __floats2half2_rn(v.x, v.y);
    __half2 b = __floats2half2_rn(v.z, v.w);
    uint2 u;
    u.x = *reinterpret_cast<unsigned*>(&a);
    u.y = *reinterpret_cast<unsigned*>(&b);
    *reinterpret_cast<uint2*>(dst + (size_t)n * DD + o) = u;
}

// half-warp hf processes adjacency entries beg+hf, beg+hf+2, ...
// 4-way unroll -> 8 rows in flight per warp
__device__ __forceinline__ void conv_body(const __half* __restrict__ tab,
                                          int base, int n, int o, int hf,
                                          float4& acc) {
    int beg = g_off[n], end = g_off[n + 1];
    int k = beg + hf;
    for (; k + 6 < end; k += 8) {
        int s0 = g_adj[k], s1 = g_adj[k + 2], s2 = g_adj[k + 4], s3 = g_adj[k + 6];
        float w0 = g_dinv[base + s0], w1 = g_dinv[base + s1];
        float w2 = g_dinv[base + s2], w3 = g_dinv[base + s3];
        float4 v0 = load_h4(tab, s0, o);
        float4 v1 = load_h4(tab, s1, o);
        float4 v2 = load_h4(tab, s2, o);
        float4 v3 = load_h4(tab, s3, o);
        acc.x += w0 * v0.x + w1 * v1.x + w2 * v2.x + w3 * v3.x;
        acc.y += w0 * v0.y + w1 * v1.y + w2 * v2.y + w3 * v3.y;
        acc.z += w0 * v0.z + w1 * v1.z + w2 * v2.z + w3 * v3.z;
        acc.w += w0 * v0.w + w1 * v1.w + w2 * v2.w + w3 * v3.w;
    }
    for (; k < end; k += 2) {
        int s = g_adj[k];
        float w = g_dinv[base + s];
        float4 v = load_h4(tab, s, o);
        acc.x += w * v.x; acc.y += w * v.y;
        acc.z += w * v.z; acc.w += w * v.w;
    }
}

__global__ void __launch_bounds__(256)
conv1_kernel() {
    int n = (blockIdx.x * blockDim.x + threadIdx.x) >> 5;
    if (n >= NTOT) return;
    int lane = threadIdx.x & 31;
    int hf = lane >> 4, sub = lane & 15;
    int o = sub << 2;

    int base = (n < NP) ? 0 : (n < NP + NT) ? NP : (NP + NT);
    const __half* tab = g_embh + (size_t)base * DD;

    float4 acc = make_float4(0.f, 0.f, 0.f, 0.f);
    conv_body(tab, base, n, o, hf, acc);

    acc.x += __shfl_xor_sync(0xffffffffu, acc.x, 16);
    acc.y += __shfl_xor_sync(0xffffffffu, acc.y, 16);
    acc.z += __shfl_xor_sync(0xffffffffu, acc.z, 16);
    acc.w += __shfl_xor_sync(0xffffffffu, acc.w, 16);

    if (hf == 0) {
        float wd = g_dinv[n];
        store_h4(g_x1h, n, o,
                 make_float4(acc.x * wd, acc.y * wd, acc.z * wd, acc.w * wd));
    }
}

__global__ void __launch_bounds__(256)
conv2_kernel() {
    int n = (blockIdx.x * blockDim.x + threadIdx.x) >> 5;
    if (n >= NTOT) return;
    int lane = threadIdx.x & 31;
    int hf = lane >> 4, sub = lane & 15;
    int o = sub << 2;

    int base = (n < NP) ? 0 : (n < NP + NT) ? NP : (NP + NT);
    const __half* tab = g_x1h + (size_t)base * DD;

    float4 acc = make_float4(0.f, 0.f, 0.f, 0.f);
    conv_body(tab, base, n, o, hf, acc);

    acc.x += __shfl_xor_sync(0xffffffffu, acc.x, 16);
    acc.y += __shfl_xor_sync(0xffffffffu, acc.y, 16);
    acc.z += __shfl_xor_sync(0xffffffffu, acc.z, 16);
    acc.w += __shfl_xor_sync(0xffffffffu, acc.w, 16);

    if (hf == 0) {
        float wd = g_dinv[n];
        float4 ev  = load_h4(g_embh, n, o);
        float4 x1v = load_h4(g_x1h, n, o);
        const float k3 = 1.f / 3.f;
        store_h4(g_x2h, n, o,
                 make_float4((ev.x + x1v.x + acc.x * wd) * k3,
                             (ev.y + x1v.y + acc.y * wd) * k3,
                             (ev.z + x1v.z + acc.z * wd) * k3,
                             (ev.w + x1v.w + acc.w * wd) * k3));
    }
}

// final fused per-edge kernel: grid-stride warp-per-edge; linear weights in
// registers (loaded once per warp-lifetime); features via broadcast LDG.128.
// half0 = src endpoint, half1 = dst endpoint; lane sub owns dims 4*sub..4*sub+3.
#define FSTEP(k, a)                                         \
    f.x = fmaf((a), w[k].x, f.x); f.y = fmaf((a), w[k].y, f.y); \
    f.z = fmaf((a), w[k].z, f.z); f.w = fmaf((a), w[k].w, f.w);

__global__ void __launch_bounds__(128)
final_kernel(const int* __restrict__ up, const int* __restrict__ ut,
             const int* __restrict__ ug,
             const float* __restrict__ sfeat, const float* __restrict__ dfeat,
             const float* __restrict__ Ws, const float* __restrict__ bs,
             const float* __restrict__ Wd, const float* __restrict__ bd,
             float* __restrict__ out) {
    int t = threadIdx.x;
    int lane = t & 31;
    int hf = lane >> 4, sub = lane & 15;
    int o = sub << 2;

    const float* Wsel = hf ? Wd : Ws;
    const float* Bsel = hf ? bd : bs;
    const float* feat = hf ? dfeat : sfeat;

    float4 w[16];
#pragma unroll
    for (int k = 0; k < 16; k++)
        w[k] = *reinterpret_cast<const float4*>(Wsel + k * 64 + o);
    float4 bias = *reinterpret_cast<const float4*>(Bsel + o);

    const __half* P = g_x2h;
    const __half* T = g_x2h + (size_t)NP * DD;
    const __half* G = g_x2h + (size_t)(NP + NT) * DD;

    int warpId = (blockIdx.x * blockDim.x + t) >> 5;
    int nWarps = (gridDim.x * blockDim.x) >> 5;
    const float k3 = 1.f / 3.f;

    for (int e = warpId; e < EE; e += nWarps) {
        // endpoint indices for this half (broadcast scalar loads)
        int i0 = up[e + hf * EE];
        int i1 = ut[e + hf * EE];
        int i2 = ug[e + hf * EE];
        // gathers (independent; issue early)
        float4 pv = load_h4(P, i0, o);
        float4 tv = load_h4(T, i1, o);
        float4 gv = load_h4(G, i2, o);

        // features: 16 floats, broadcast float4 loads
        const float4* fx = reinterpret_cast<const float4*>(feat + (size_t)e * 16);
        float4 x0 = fx[0], x1 = fx[1], x2 = fx[2], x3 = fx[3];

        float4 f = bias;
        FSTEP(0,  x0.x) FSTEP(1,  x0.y) FSTEP(2,  x0.z) FSTEP(3,  x0.w)
        FSTEP(4,  x1.x) FSTEP(5,  x1.y) FSTEP(6,  x1.z) FSTEP(7,  x1.w)
        FSTEP(8,  x2.x) FSTEP(9,  x2.y) FSTEP(10, x2.z) FSTEP(11, x2.w)
        FSTEP(12, x3.x) FSTEP(13, x3.y) FSTEP(14, x3.z) FSTEP(15, x3.w)

        float4 me;
        me.x = (pv.x + tv.x + gv.x) * k3 + f.x;
        me.y = (pv.y + tv.y + gv.y) * k3 + f.y;
        me.z = (pv.z + tv.z + gv.z) * k3 + f.z;
        me.w = (pv.w + tv.w + gv.w) * k3 + f.w;

        float4 ot;
        ot.x = __shfl_xor_sync(0xffffffffu, me.x, 16);
        ot.y = __shfl_xor_sync(0xffffffffu, me.y, 16);
        ot.z = __shfl_xor_sync(0xffffffffu, me.z, 16);
        ot.w = __shfl_xor_sync(0xffffffffu, me.w, 16);

        float partial = me.x * ot.x + me.y * ot.y + me.z * ot.z + me.w * ot.w;
#pragma unroll
        for (int off = 8; off; off >>= 1)
            partial += __shfl_xor_sync(0xffffffffu, partial, off);
        if (lane == 0) out[e] = partial;
    }
}

// ---------------------------------------------------------------
extern "C" void kernel_launch(void* const* d_in, const int* in_sizes, int n_in,
                              void* d_out, int out_size) {
    const int*   up     = (const int*)d_in[0];
    const int*   ut     = (const int*)d_in[1];
    const int*   ug     = (const int*)d_in[2];
    const float* sfeat  = (const float*)d_in[3];
    const float* dfeat  = (const float*)d_in[4];
    const float* up_emb = (const float*)d_in[5];
    const float* ut_emb = (const float*)d_in[6];
    const float* ug_emb = (const float*)d_in[7];
    const float* W_src  = (const float*)d_in[8];
    const float* b_src  = (const float*)d_in[9];
    const float* W_dst  = (const float*)d_in[10];
    const float* b_dst  = (const float*)d_in[11];
    float* out = (float*)d_out;

    void* degPtr = nullptr;
    cudaGetSymbolAddress(&degPtr, g_deg);
    cudaMemsetAsync(degPtr, 0, NTOT * sizeof(int));

    convert_kernel<<<(NTOT * DD / 8 + 255) / 256, 256>>>(up_emb, ut_emb, ug_emb);
    degree_kernel<<<(3 * (EE / 4) + 255) / 256, 256>>>(up, ut, ug);
    scan1_kernel<<<NBLK, 256>>>();
    scan2_kernel<<<1, 256>>>();
    scan3_kernel<<<(NTOT + 255) / 256, 256>>>();
    build_adj_kernel<<<(3 * (EE / 4) + 255) / 256, 256>>>(up, ut, ug);

    const int convGrid = (NTOT * 32 + 255) / 256;
    conv1_kernel<<<convGrid, 256>>>();
    conv2_kernel<<<convGrid, 256>>>();

    // 2048 blocks x 128 thr = 8192 warps; ~61 edges per warp
    final_kernel<<<2048, 128>>>(up, ut, ug, sfeat, dfeat,
                                W_src, b_src, W_dst, b_dst, out);
}

// round 7
// speedup vs baseline: 1.2299x; 1.2299x over previous
#include <cuda_runtime.h>
#include <cuda_fp16.h>

#define NP 110000
#define NT 20000
#define NG 10000
#define NTOT (NP + NT + NG)   // 140000
#define EE 500000
#define DD 64

#define SCAN_BLK ((NTOT + 1023) / 1024)   // 137

// ---- scratch (static device memory; no allocations allowed) ----
__device__ int   g_deg[NTOT];
__device__ int   g_off[NTOT];
__device__ int   g_cur[NTOT];
__device__ int   g_total;
__device__ int   g_adj[3 * EE];
__device__ float g_dinv[NTOT];
__device__ __align__(16) __half g_x1h[(size_t)NTOT * DD];   // layer-1 output
__device__ __align__(16) __half g_x2h[(size_t)NTOT * DD];   // final table p

// ---------------------------------------------------------------
__global__ void degree_kernel(const int* __restrict__ up,
                              const int* __restrict__ ut,
                              const int* __restrict__ ug) {
    const int Q = EE / 4;
    int i = blockIdx.x * blockDim.x + threadIdx.x;
    if (i < Q) {
        int4 d = reinterpret_cast<const int4*>(up + EE)[i];
        atomicAdd(&g_deg[d.x], 1); atomicAdd(&g_deg[d.y], 1);
        atomicAdd(&g_deg[d.z], 1); atomicAdd(&g_deg[d.w], 1);
    } else if (i < 2 * Q) {
        int4 d = reinterpret_cast<const int4*>(ut + EE)[i - Q];
        atomicAdd(&g_deg[NP + d.x], 1); atomicAdd(&g_deg[NP + d.y], 1);
        atomicAdd(&g_deg[NP + d.z], 1); atomicAdd(&g_deg[NP + d.w], 1);
    } else if (i < 3 * Q) {
        int4 d = reinterpret_cast<const int4*>(ug + EE)[i - 2 * Q];
        atomicAdd(&g_deg[NP + NT + d.x], 1); atomicAdd(&g_deg[NP + NT + d.y], 1);
        atomicAdd(&g_deg[NP + NT + d.z], 1); atomicAdd(&g_deg[NP + NT + d.w], 1);
    }
}

// single-pass scan: block-local prefix + atomic global base.
// CSR offsets need NOT be globally ordered (rows read as [off, off+deg)).
__global__ void scanA_kernel() {
    __shared__ int wsum[8];
    __shared__ int blockBase;
    int t = threadIdx.x, lane = t & 31, wid = t >> 5;
    int idx = blockIdx.x * 1024 + t * 4;

    int v0 = 0, v1 = 0, v2 = 0, v3 = 0;
    if (idx + 3 < NTOT) {
        int4 d4 = *reinterpret_cast<const int4*>(g_deg + idx);
        v0 = d4.x; v1 = d4.y; v2 = d4.z; v3 = d4.w;
    } else {
        if (idx     < NTOT) v0 = g_deg[idx];
        if (idx + 1 < NTOT) v1 = g_deg[idx + 1];
        if (idx + 2 < NTOT) v2 = g_deg[idx + 2];
        if (idx + 3 < NTOT) v3 = g_deg[idx + 3];
    }
    int s = v0 + v1 + v2 + v3;
    int inc = s;
#pragma unroll
    for (int o = 1; o < 32; o <<= 1) {
        int n = __shfl_up_sync(0xffffffffu, inc, o);
        if (lane >= o) inc += n;
    }
    if (lane == 31) wsum[wid] = inc;
    __syncthreads();
    if (t == 0) {
        int run = 0;
#pragma unroll
        for (int w = 0; w < 8; w++) { int x = wsum[w]; wsum[w] = run; run += x; }
        blockBase = atomicAdd(&g_total, run);
    }
    __syncthreads();
    int ex = blockBase + wsum[wid] + inc - s;
    if (idx     < NTOT) { g_off[idx]     = ex;               g_cur[idx]     = ex;
                          g_dinv[idx]     = v0 ? rsqrtf((float)v0) : 0.f; }
    if (idx + 1 < NTOT) { g_off[idx + 1] = ex + v0;          g_cur[idx + 1] = ex + v0;
                          g_dinv[idx + 1] = v1 ? rsqrtf((float)v1) : 0.f; }
    if (idx + 2 < NTOT) { g_off[idx + 2] = ex + v0 + v1;     g_cur[idx + 2] = ex + v0 + v1;
                          g_dinv[idx + 2] = v2 ? rsqrtf((float)v2) : 0.f; }
    if (idx + 3 < NTOT) { g_off[idx + 3] = ex + v0 + v1 + v2; g_cur[idx + 3] = ex + v0 + v1 + v2;
                          g_dinv[idx + 3] = v3 ? rsqrtf((float)v3) : 0.f; }
}

__global__ void build_adj_kernel(const int* __restrict__ up,
                                 const int* __restrict__ ut,
                                 const int* __restrict__ ug) {
    const int Q = EE / 4;
    int i = blockIdx.x * blockDim.x + threadIdx.x;
    if (i < Q) {
        int4 s = reinterpret_cast<const int4*>(up)[i];
        int4 d = reinterpret_cast<const int4*>(up + EE)[i];
        g_adj[atomicAdd(&g_cur[d.x], 1)] = s.x;
        g_adj[atomicAdd(&g_cur[d.y], 1)] = s.y;
        g_adj[atomicAdd(&g_cur[d.z], 1)] = s.z;
        g_adj[atomicAdd(&g_cur[d.w], 1)] = s.w;
    } else if (i < 2 * Q) {
        int4 s = reinterpret_cast<const int4*>(ut)[i - Q];
        int4 d = reinterpret_cast<const int4*>(ut + EE)[i - Q];
        g_adj[atomicAdd(&g_cur[NP + d.x], 1)] = s.x;
        g_adj[atomicAdd(&g_cur[NP + d.y], 1)] = s.y;
        g_adj[atomicAdd(&g_cur[NP + d.z], 1)] = s.z;
        g_adj[atomicAdd(&g_cur[NP + d.w], 1)] = s.w;
    } else if (i < 3 * Q) {
        int4 s = reinterpret_cast<const int4*>(ug)[i - 2 * Q];
        int4 d = reinterpret_cast<const int4*>(ug + EE)[i - 2 * Q];
        g_adj[atomicAdd(&g_cur[NP + NT + d.x], 1)] = s.x;
        g_adj[atomicAdd(&g_cur[NP + NT + d.y], 1)] = s.y;
        g_adj[atomicAdd(&g_cur[NP + NT + d.z], 1)] = s.z;
        g_adj[atomicAdd(&g_cur[NP + NT + d.w], 1)] = s.w;
    }
}

// ---------------------------------------------------------------
__device__ __forceinline__ float4 load_h4(const __half* __restrict__ tab,
                                          int s, int o) {
    uint2 r = *reinterpret_cast<const uint2*>(tab + (size_t)s * DD + o);
    __half2 a = *reinterpret_cast<__half2*>(&r.x);
    __half2 b = *reinterpret_cast<__half2*>(&r.y);
    float2 fa = __half22float2(a), fb = __half22float2(b);
    return make_float4(fa.x, fa.y, fb.x, fb.y);
}

__device__ __forceinline__ void store_h4(__half* __restrict__ dst,
                                         int n, int o, float4 v) {
    __half2 a = __floats2half2_rn(v.x, v.y);
    __half2 b = __floats2half2_rn(v.z, v.w);
    uint2 u;
    u.x = *reinterpret_cast<unsigned*>(&a);
    u.y = *reinterpret_cast<unsigned*>(&b);
    *reinterpret_cast<uint2*>(dst + (size_t)n * DD + o) = u;
}

// conv1: gathers fp32 embedding rows, writes fp16 x1.
// half-warp hf handles entries beg+hf, beg+hf+2, ...; lane sub owns 4 dims.
__global__ void __launch_bounds__(256)
conv1_kernel(const float* __restrict__ e0, const float* __restrict__ e1,
             const float* __restrict__ e2) {
    int n = (blockIdx.x * blockDim.x + threadIdx.x) >> 5;
    if (n >= NTOT) return;
    int lane = threadIdx.x & 31;
    int hf = lane >> 4, sub = lane & 15;
    int o = sub << 2;

    const float* tab;
    int base;
    if (n < NP)            { tab = e0; base = 0; }
    else if (n < NP + NT)  { tab = e1; base = NP; }
    else                   { tab = e2; base = NP + NT; }

    int beg = g_off[n], end = beg + g_deg[n];
    float4 acc = make_float4(0.f, 0.f, 0.f, 0.f);
    int k = beg + hf;
    for (; k + 6 < end; k += 8) {
        int s0 = g_adj[k], s1 = g_adj[k + 2], s2 = g_adj[k + 4], s3 = g_adj[k + 6];
        float w0 = g_dinv[base + s0], w1 = g_dinv[base + s1];
        float w2 = g_dinv[base + s2], w3 = g_dinv[base + s3];
        float4 v0 = *reinterpret_cast<const float4*>(tab + (size_t)s0 * DD + o);
        float4 v1 = *reinterpret_cast<const float4*>(tab + (size_t)s1 * DD + o);
        float4 v2 = *reinterpret_cast<const float4*>(tab + (size_t)s2 * DD + o);
        float4 v3 = *reinterpret_cast<const float4*>(tab + (size_t)s3 * DD + o);
        acc.x += w0 * v0.x + w1 * v1.x + w2 * v2.x + w3 * v3.x;
        acc.y += w0 * v0.y + w1 * v1.y + w2 * v2.y + w3 * v3.y;
        acc.z += w0 * v0.z + w1 * v1.z + w2 * v2.z + w3 * v3.z;
        acc.w += w0 * v0.w + w1 * v1.w + w2 * v2.w + w3 * v3.w;
    }
    for (; k < end; k += 2) {
        int s = g_adj[k];
        float w = g_dinv[base + s];
        float4 v = *reinterpret_cast<const float4*>(tab + (size_t)s * DD + o);
        acc.x += w * v.x; acc.y += w * v.y;
        acc.z += w * v.z; acc.w += w * v.w;
    }

    acc.x += __shfl_xor_sync(0xffffffffu, acc.x, 16);
    acc.y += __shfl_xor_sync(0xffffffffu, acc.y, 16);
    acc.z += __shfl_xor_sync(0xffffffffu, acc.z, 16);
    acc.w += __shfl_xor_sync(0xffffffffu, acc.w, 16);

    if (hf == 0) {
        float wd = g_dinv[n];
        store_h4(g_x1h, n, o,
                 make_float4(acc.x * wd, acc.y * wd, acc.z * wd, acc.w * wd));
    }
}

// conv2: gathers fp16 x1 rows; epilogue reads fp32 emb coalesced; writes fp16 p.
__global__ void __launch_bounds__(256)
conv2_kernel(const float* __restrict__ e0, const float* __restrict__ e1,
             const float* __restrict__ e2) {
    int n = (blockIdx.x * blockDim.x + threadIdx.x) >> 5;
    if (n >= NTOT) return;
    int lane = threadIdx.x & 31;
    int hf = lane >> 4, sub = lane & 15;
    int o = sub << 2;

    const float* emb;
    int base;
    if (n < NP)            { emb = e0; base = 0; }
    else if (n < NP + NT)  { emb = e1; base = NP; }
    else                   { emb = e2; base = NP + NT; }
    const __half* tab = g_x1h + (size_t)base * DD;

    int beg = g_off[n], end = beg + g_deg[n];
    float4 acc = make_float4(0.f, 0.f, 0.f, 0.f);
    int k = beg + hf;
    for (; k + 6 < end; k += 8) {
        int s0 = g_adj[k], s1 = g_adj[k + 2], s2 = g_adj[k + 4], s3 = g_adj[k + 6];
        float w0 = g_dinv[base + s0], w1 = g_dinv[base + s1];
        float w2 = g_dinv[base + s2], w3 = g_dinv[base + s3];
        float4 v0 = load_h4(tab, s0, o);
        float4 v1 = load_h4(tab, s1, o);
        float4 v2 = load_h4(tab, s2, o);
        float4 v3 = load_h4(tab, s3, o);
        acc.x += w0 * v0.x + w1 * v1.x + w2 * v2.x + w3 * v3.x;
        acc.y += w0 * v0.y + w1 * v1.y + w2 * v2.y + w3 * v3.y;
        acc.z += w0 * v0.z + w1 * v1.z + w2 * v2.z + w3 * v3.z;
        acc.w += w0 * v0.w + w1 * v1.w + w2 * v2.w + w3 * v3.w;
    }
    for (; k < end; k += 2) {
        int s = g_adj[k];
        float w = g_dinv[base + s];
        float4 v = load_h4(tab, s, o);
        acc.x += w * v.x; acc.y += w * v.y;
        acc.z += w * v.z; acc.w += w * v.w;
    }

    acc.x += __shfl_xor_sync(0xffffffffu, acc.x, 16);
    acc.y += __shfl_xor_sync(0xffffffffu, acc.y, 16);
    acc.z += __shfl_xor_sync(0xffffffffu, acc.z, 16);
    acc.w += __shfl_xor_sync(0xffffffffu, acc.w, 16);

    if (hf == 0) {
        float wd = g_dinv[n];
        float4 ev  = *reinterpret_cast<const float4*>(emb + (size_t)(n - base) * DD + o);
        float4 x1v = load_h4(g_x1h, n, o);
        const float k3 = 1.f / 3.f;
        store_h4(g_x2h, n, o,
                 make_float4((ev.x + x1v.x + acc.x * wd) * k3,
                             (ev.y + x1v.y + acc.y * wd) * k3,
                             (ev.z + x1v.z + acc.z * wd) * k3,
                             (ev.w + x1v.w + acc.w * wd) * k3));
    }
}

// final: warp-per-edge-pair, weights in registers, 12 gathers in flight.
#define FSTEP(f, k, a)                                            \
    f.x = fmaf((a), w[k].x, f.x); f.y = fmaf((a), w[k].y, f.y);   \
    f.z = fmaf((a), w[k].z, f.z); f.w = fmaf((a), w[k].w, f.w);

__global__ void __launch_bounds__(128)
final_kernel(const int* __restrict__ up, const int* __restrict__ ut,
             const int* __restrict__ ug,
             const float* __restrict__ sfeat, const float* __restrict__ dfeat,
             const float* __restrict__ Ws, const float* __restrict__ bs,
             const float* __restrict__ Wd, const float* __restrict__ bd,
             float* __restrict__ out) {
    int t = threadIdx.x;
    int lane = t & 31;
    int hf = lane >> 4, sub = lane & 15;
    int o = sub << 2;

    const float* Wsel = hf ? Wd : Ws;
    const float* Bsel = hf ? bd : bs;
    const float* feat = hf ? dfeat : sfeat;

    float4 w[16];
#pragma unroll
    for (int k = 0; k < 16; k++)
        w[k] = *reinterpret_cast<const float4*>(Wsel + k * 64 + o);
    float4 bias = *reinterpret_cast<const float4*>(Bsel + o);

    const __half* P = g_x2h;
    const __half* T = g_x2h + (size_t)NP * DD;
    const __half* G = g_x2h + (size_t)(NP + NT) * DD;

    int warpId = (blockIdx.x * blockDim.x + t) >> 5;
    int nWarps = (gridDim.x * blockDim.x) >> 5;
    const float k3 = 1.f / 3.f;

    for (int e = warpId * 2; e < EE; e += nWarps * 2) {
        int eb = e + 1;   // EE even, e even -> eb < EE always
        // indices for both edges (this half's endpoint)
        int a0 = up[e + hf * EE],  a1 = ut[e + hf * EE],  a2 = ug[e + hf * EE];
        int b0 = up[eb + hf * EE], b1 = ut[eb + hf * EE], b2 = ug[eb + hf * EE];
        // 6 gathers in flight
        float4 pa = load_h4(P, a0, o), ta = load_h4(T, a1, o), ga = load_h4(G, a2, o);
        float4 pb = load_h4(P, b0, o), tb = load_h4(T, b1, o), gb = load_h4(G, b2, o);
        // features (contiguous 128B for the pair)
        const float4* fxa = reinterpret_cast<const float4*>(feat + (size_t)e * 16);
        float4 xa0 = fxa[0], xa1 = fxa[1], xa2 = fxa[2], xa3 = fxa[3];
        float4 xb0 = fxa[4], xb1 = fxa[5], xb2 = fxa[6], xb3 = fxa[7];

        float4 fA = bias;
        FSTEP(fA, 0,  xa0.x) FSTEP(fA, 1,  xa0.y) FSTEP(fA, 2,  xa0.z) FSTEP(fA, 3,  xa0.w)
        FSTEP(fA, 4,  xa1.x) FSTEP(fA, 5,  xa1.y) FSTEP(fA, 6,  xa1.z) FSTEP(fA, 7,  xa1.w)
        FSTEP(fA, 8,  xa2.x) FSTEP(fA, 9,  xa2.y) FSTEP(fA, 10, xa2.z) FSTEP(fA, 11, xa2.w)
        FSTEP(fA, 12, xa3.x) FSTEP(fA, 13, xa3.y) FSTEP(fA, 14, xa3.z) FSTEP(fA, 15, xa3.w)

        float4 fB = bias;
        FSTEP(fB, 0,  xb0.x) FSTEP(fB, 1,  xb0.y) FSTEP(fB, 2,  xb0.z) FSTEP(fB, 3,  xb0.w)
        FSTEP(fB, 4,  xb1.x) FSTEP(fB, 5,  xb1.y) FSTEP(fB, 6,  xb1.z) FSTEP(fB, 7,  xb1.w)
        FSTEP(fB, 8,  xb2.x) FSTEP(fB, 9,  xb2.y) FSTEP(fB, 10, xb2.z) FSTEP(fB, 11, xb2.w)
        FSTEP(fB, 12, xb3.x) FSTEP(fB, 13, xb3.y) FSTEP(fB, 14, xb3.z) FSTEP(fB, 15, xb3.w)

        float4 meA, meB;
        meA.x = (pa.x + ta.x + ga.x) * k3 + fA.x;
        meA.y = (pa.y + ta.y + ga.y) * k3 + fA.y;
        meA.z = (pa.z + ta.z + ga.z) * k3 + fA.z;
        meA.w = (pa.w + ta.w + ga.w) * k3 + fA.w;
        meB.x = (pb.x + tb.x + gb.x) * k3 + fB.x;
        meB.y = (pb.y + tb.y + gb.y) * k3 + fB.y;
        meB.z = (pb.z + tb.z + gb.z) * k3 + fB.z;
        meB.w = (pb.w + tb.w + gb.w) * k3 + fB.w;

        float4 otA, otB;
        otA.x = __shfl_xor_sync(0xffffffffu, meA.x, 16);
        otA.y = __shfl_xor_sync(0xffffffffu, meA.y, 16);
        otA.z = __shfl_xor_sync(0xffffffffu, meA.z, 16);
        otA.w = __shfl_xor_sync(0xffffffffu, meA.w, 16);
        otB.x = __shfl_xor_sync(0xffffffffu, meB.x, 16);
        otB.y = __shfl_xor_sync(0xffffffffu, meB.y, 16);
        otB.z = __shfl_xor_sync(0xffffffffu, meB.z, 16);
        otB.w = __shfl_xor_sync(0xffffffffu, meB.w, 16);

        float pA = meA.x * otA.x + meA.y * otA.y + meA.z * otA.z + meA.w * otA.w;
        float pB = meB.x * otB.x + meB.y * otB.y + meB.z * otB.z + meB.w * otB.w;
#pragma unroll
        for (int off = 8; off; off >>= 1) {
            pA += __shfl_xor_sync(0xffffffffu, pA, off);
            pB += __shfl_xor_sync(0xffffffffu, pB, off);
        }
        if (lane == 0) { out[e] = pA; out[eb] = pB; }
    }
}

// ---------------------------------------------------------------
extern "C" void kernel_launch(void* const* d_in, const int* in_sizes, int n_in,
                              void* d_out, int out_size) {
    const int*   up     = (const int*)d_in[0];
    const int*   ut     = (const int*)d_in[1];
    const int*   ug     = (const int*)d_in[2];
    const float* sfeat  = (const float*)d_in[3];
    const float* dfeat  = (const float*)d_in[4];
    const float* up_emb = (const float*)d_in[5];
    const float* ut_emb = (const float*)d_in[6];
    const float* ug_emb = (const float*)d_in[7];
    const float* W_src  = (const float*)d_in[8];
    const float* b_src  = (const float*)d_in[9];
    const float* W_dst  = (const float*)d_in[10];
    const float* b_dst  = (const float*)d_in[11];
    float* out = (float*)d_out;

    void* degPtr = nullptr;  cudaGetSymbolAddress(&degPtr, g_deg);
    void* totPtr = nullptr;  cudaGetSymbolAddress(&totPtr, g_total);
    cudaMemsetAsync(degPtr, 0, NTOT * sizeof(int));
    cudaMemsetAsync(totPtr, 0, sizeof(int));

    degree_kernel<<<(3 * (EE / 4) + 255) / 256, 256>>>(up, ut, ug);
    scanA_kernel<<<SCAN_BLK, 256>>>();
    build_adj_kernel<<<(3 * (EE / 4) + 255) / 256, 256>>>(up, ut, ug);

    const int convGrid = (NTOT * 32 + 255) / 256;
    conv1_kernel<<<convGrid, 256>>>(up_emb, ut_emb, ug_emb);   // profiled slot
    conv2_kernel<<<convGrid, 256>>>(up_emb, ut_emb, ug_emb);

    final_kernel<<<4096, 128>>>(up, ut, ug, sfeat, dfeat,
                                W_src, b_src, W_dst, b_dst, out);
}